// round 13
// baseline (speedup 1.0000x reference)
#include <cuda_runtime.h>
#include <math.h>
#include <stdint.h>

#define D        2048
#define NEXP     64
#define NTOK     16384
#define SCALE    21.166666f          // 127/6: LN outputs ~N(0,1), 6-sigma clip = never
#define MARGIN_I 6700                // 15 normalized units * SCALE^2 (~12 sigma_diff)
#define INVT     (1.f / 45.254833995939045f)  // 1/sqrt(2048)

// ---------- int8 screen GEMM geometry ----------
#define TMQ      128                 // tokens per CTA
#define KCQ      128                 // int8 k per chunk
#define QCH      (D / KCQ)           // 16
#define QPITCH   144                 // bytes per smem row (pad)
#define QA_BYTES (TMQ * QPITCH)      // 18432
#define QB_BYTES (NEXP * QPITCH)     // 9216
#define QSTAGE   (QA_BYTES + QB_BYTES)
#define QSTAGES  3
#define QSMEM    (QSTAGES * QSTAGE)  // 82944
#define NCAND    16

// ---------- rescore v3 geometry (3-stage: prefetch distance 2 < stages) ----------
#define RTOK     128                 // tokens per CTA
#define RKC      64                  // fp32 k per chunk
#define RNCH     (D / RKC)           // 32
#define RPITCHB  272                 // bytes per smem row (68 floats: LDS.128 conflict-free)
#define RX_BYTES (RTOK * RPITCHB)    // 34816
#define RE_BYTES (NEXP * RPITCHB)    // 17408
#define RSTAGE   (RX_BYTES + RE_BYTES) // 52224
#define RSTAGES  3
#define RSMEM    (RSTAGES * RSTAGE)  // 156672

__device__ float    g_enorm[NEXP * D];     // normalized experts fp32
__device__ float    g_esum[NEXP];
__device__ uint32_t g_eq[NEXP * D / 4];    // int8 experts, packed
__device__ uint32_t g_q[(size_t)NTOK * D / 4];  // int8 tokens, packed (32MB)
__device__ float2   g_tokstats[NTOK];      // (mu, rstd)
__device__ unsigned long long g_mask[NTOK];

typedef unsigned long long u64;

__device__ __forceinline__ void cp_async16(uint32_t dst, const void* src) {
    asm volatile("cp.async.cg.shared.global [%0], [%1], 16;"
                 :: "r"(dst), "l"(src) : "memory");
}
__device__ __forceinline__ int dp4a(uint32_t a, uint32_t b, int c) {
    int r;
    asm("dp4a.s32.s32 %0, %1, %2, %3;" : "=r"(r) : "r"(a), "r"(b), "r"(c));
    return r;
}
__device__ __forceinline__ uint32_t q8(float x) {
    int v = __float2int_rn(x * SCALE);
    v = max(-127, min(127, v));
    return (uint32_t)v & 0xFFu;
}
__device__ __forceinline__ float2 block_reduce256_2(float a, float b, float2* red) {
    int tid = threadIdx.x;
    __syncthreads();
    #pragma unroll
    for (int o = 16; o > 0; o >>= 1) {
        a += __shfl_xor_sync(0xffffffffu, a, o);
        b += __shfl_xor_sync(0xffffffffu, b, o);
    }
    if ((tid & 31) == 0) red[tid >> 5] = make_float2(a, b);
    __syncthreads();
    float2 r = (tid < 8) ? red[tid] : make_float2(0.f, 0.f);
    #pragma unroll
    for (int o = 4; o > 0; o >>= 1) {
        r.x += __shfl_xor_sync(0xffffffffu, r.x, o);
        r.y += __shfl_xor_sync(0xffffffffu, r.y, o);
    }
    if (tid == 0) red[0] = r;
    __syncthreads();
    return red[0];
}

// ---------- kernel 0: normalize experts -> fp32 + int8 + sums ----------
__global__ __launch_bounds__(256) void normalize_experts(const float* __restrict__ emb) {
    __shared__ float2 red[8];
    const int e = blockIdx.x, tid = threadIdx.x;
    const float4* row = reinterpret_cast<const float4*>(emb + e * D);
    float4 v0 = row[tid];
    float4 v1 = row[tid + 256];
    float s  = v0.x + v0.y + v0.z + v0.w + v1.x + v1.y + v1.z + v1.w;
    float sq = v0.x*v0.x + v0.y*v0.y + v0.z*v0.z + v0.w*v0.w
             + v1.x*v1.x + v1.y*v1.y + v1.z*v1.z + v1.w*v1.w;
    float2 ssq = block_reduce256_2(s, sq, red);
    const float mu   = ssq.x * (1.f / D);
    const float var  = ssq.y * (1.f / D) - mu * mu;
    const float rstd = rsqrtf(var + 1e-5f);

    float4 n0 = make_float4((v0.x-mu)*rstd, (v0.y-mu)*rstd, (v0.z-mu)*rstd, (v0.w-mu)*rstd);
    float4 n1 = make_float4((v1.x-mu)*rstd, (v1.y-mu)*rstd, (v1.z-mu)*rstd, (v1.w-mu)*rstd);
    float4* o = reinterpret_cast<float4*>(g_enorm + e * D);
    o[tid]       = n0;
    o[tid + 256] = n1;
    g_eq[e * 512 + tid]       = q8(n0.x) | (q8(n0.y) << 8) | (q8(n0.z) << 16) | (q8(n0.w) << 24);
    g_eq[e * 512 + 256 + tid] = q8(n1.x) | (q8(n1.y) << 8) | (q8(n1.z) << 16) | (q8(n1.w) << 24);

    float ls = n0.x+n0.y+n0.z+n0.w + n1.x+n1.y+n1.z+n1.w;
    float2 lz = block_reduce256_2(ls, 0.f, red);
    if (tid == 0) g_esum[e] = lz.x;
}

// ---------- kernel P1: token LN stats + int8 quantize ----------
__global__ __launch_bounds__(256) void quant_kernel(const float* __restrict__ x) {
    const int w    = threadIdx.x >> 5;
    const int lane = threadIdx.x & 31;
    const int t    = blockIdx.x * 8 + w;

    const float4* row = reinterpret_cast<const float4*>(x + (size_t)t * D);
    float4 v[16];
    float s = 0.f, sq = 0.f;
    #pragma unroll
    for (int i = 0; i < 16; i++) {
        v[i] = row[i * 32 + lane];
        s  += v[i].x + v[i].y + v[i].z + v[i].w;
        sq += v[i].x*v[i].x + v[i].y*v[i].y + v[i].z*v[i].z + v[i].w*v[i].w;
    }
    #pragma unroll
    for (int o = 16; o > 0; o >>= 1) {
        s  += __shfl_xor_sync(0xffffffffu, s, o);
        sq += __shfl_xor_sync(0xffffffffu, sq, o);
    }
    const float mu   = s * (1.f / D);
    const float rstd = rsqrtf(sq * (1.f / D) - mu * mu + 1e-5f);

    uint32_t* qrow = g_q + (size_t)t * 512;
    #pragma unroll
    for (int i = 0; i < 16; i++) {
        float a0 = (v[i].x - mu) * rstd, a1 = (v[i].y - mu) * rstd;
        float a2 = (v[i].z - mu) * rstd, a3 = (v[i].w - mu) * rstd;
        qrow[i * 32 + lane] = q8(a0) | (q8(a1) << 8) | (q8(a2) << 16) | (q8(a3) << 24);
    }
    if (lane == 0) g_tokstats[t] = make_float2(mu, rstd);
}

// ---------- kernel P2: int8 dp4a screen GEMM -> candidate masks (UNCHANGED) ----------
__global__ __launch_bounds__(256, 1) void screen_kernel() {
    extern __shared__ __align__(128) char smem[];
    const uint32_t sb = (uint32_t)__cvta_generic_to_shared(smem);
    const int tid = threadIdx.x;
    const int tg  = tid & 15;
    const int eg  = tid >> 4;
    const int m0  = blockIdx.x * TMQ;

    const char* qa = (const char*)g_q + (size_t)m0 * D;
    const char* qb = (const char*)g_eq;

    #define QISSUE(c) do {                                                     \
        uint32_t base_ = sb + ((c) % QSTAGES) * QSTAGE;                        \
        _Pragma("unroll")                                                      \
        for (int i_ = 0; i_ < 4; i_++) {                                       \
            int idx_ = tid + i_ * 256;                                         \
            int r_ = idx_ >> 3, sg_ = idx_ & 7;                                \
            cp_async16(base_ + r_ * QPITCH + sg_ * 16,                         \
                       qa + (size_t)r_ * D + (c) * KCQ + sg_ * 16);            \
        }                                                                      \
        _Pragma("unroll")                                                      \
        for (int i_ = 0; i_ < 2; i_++) {                                       \
            int idx_ = tid + i_ * 256;                                         \
            int r_ = idx_ >> 3, sg_ = idx_ & 7;                                \
            cp_async16(base_ + QA_BYTES + r_ * QPITCH + sg_ * 16,              \
                       qb + (size_t)r_ * D + (c) * KCQ + sg_ * 16);            \
        }                                                                      \
    } while (0)

    QISSUE(0); asm volatile("cp.async.commit_group;" ::: "memory");
    QISSUE(1); asm volatile("cp.async.commit_group;" ::: "memory");

    int acc[8][4];
    #pragma unroll
    for (int i = 0; i < 8; i++)
        #pragma unroll
        for (int j = 0; j < 4; j++) acc[i][j] = 0;

    for (int c = 0; c < QCH; c++) {
        asm volatile("cp.async.wait_group 1;" ::: "memory");
        __syncthreads();
        if (c + 2 < QCH) QISSUE(c + 2);
        asm volatile("cp.async.commit_group;" ::: "memory");

        const uint32_t base  = sb + (c % QSTAGES) * QSTAGE;
        const uint32_t abase = base + tg * QPITCH;
        const uint32_t bbase = base + QA_BYTES + (eg * 4) * QPITCH;

        #pragma unroll
        for (int kq = 0; kq < 8; kq++) {
            uint32_t b0x,b0y,b0z,b0w, b1x,b1y,b1z,b1w, b2x,b2y,b2z,b2w, b3x,b3y,b3z,b3w;
            asm volatile("ld.shared.v4.b32 {%0,%1,%2,%3}, [%4];"
                         : "=r"(b0x),"=r"(b0y),"=r"(b0z),"=r"(b0w) : "r"(bbase + kq*16));
            asm volatile("ld.shared.v4.b32 {%0,%1,%2,%3}, [%4];"
                         : "=r"(b1x),"=r"(b1y),"=r"(b1z),"=r"(b1w) : "r"(bbase + QPITCH + kq*16));
            asm volatile("ld.shared.v4.b32 {%0,%1,%2,%3}, [%4];"
                         : "=r"(b2x),"=r"(b2y),"=r"(b2z),"=r"(b2w) : "r"(bbase + 2*QPITCH + kq*16));
            asm volatile("ld.shared.v4.b32 {%0,%1,%2,%3}, [%4];"
                         : "=r"(b3x),"=r"(b3y),"=r"(b3z),"=r"(b3w) : "r"(bbase + 3*QPITCH + kq*16));
            #pragma unroll
            for (int i = 0; i < 8; i++) {
                uint32_t ax, ay, az, aw;
                asm volatile("ld.shared.v4.b32 {%0,%1,%2,%3}, [%4];"
                             : "=r"(ax),"=r"(ay),"=r"(az),"=r"(aw)
                             : "r"(abase + i * 16 * QPITCH + kq * 16));
                acc[i][0] = dp4a(aw, b0w, dp4a(az, b0z, dp4a(ay, b0y, dp4a(ax, b0x, acc[i][0]))));
                acc[i][1] = dp4a(aw, b1w, dp4a(az, b1z, dp4a(ay, b1y, dp4a(ax, b1x, acc[i][1]))));
                acc[i][2] = dp4a(aw, b2w, dp4a(az, b2z, dp4a(ay, b2y, dp4a(ax, b2x, acc[i][2]))));
                acc[i][3] = dp4a(aw, b3w, dp4a(az, b3z, dp4a(ay, b3y, dp4a(ax, b3x, acc[i][3]))));
            }
        }
    }
    asm volatile("cp.async.wait_all;" ::: "memory");
    __syncthreads();

    int* simI = reinterpret_cast<int*>(smem);      // [128][68]
    #pragma unroll
    for (int i = 0; i < 8; i++)
        asm volatile("st.shared.v4.b32 [%0], {%1,%2,%3,%4};"
                     :: "r"(sb + ((i * 16 + tg) * 68 + eg * 4) * 4),
                        "r"(acc[i][0]), "r"(acc[i][1]), "r"(acc[i][2]), "r"(acc[i][3])
                     : "memory");
    __syncthreads();

    if (tid < TMQ) {
        const int* r = simI + tid * 68;
        int v1 = -2147483647, v2 = -2147483647;
        #pragma unroll 8
        for (int e = 0; e < NEXP; e++) {
            int v = r[e];
            if (v > v1)      { v2 = v1; v1 = v; }
            else if (v > v2) { v2 = v; }
        }
        const int thr = v2 - MARGIN_I;
        u64 mask = 0ull; int cnt = 0;
        #pragma unroll 8
        for (int e = 0; e < NEXP; e++)
            if (r[e] >= thr) { mask |= 1ull << e; cnt++; }
        if (cnt > NCAND) {
            u64 keep = 0ull;
            for (int it = 0; it < NCAND; it++) {
                int best = -2147483647, bi = -1;
                for (int e = 0; e < NEXP; e++)
                    if ((mask >> e) & 1ull)
                        if (!((keep >> e) & 1ull) && r[e] > best) { best = r[e]; bi = e; }
                keep |= 1ull << bi;
            }
            mask = keep;
        }
        g_mask[m0 + tid] = mask;
    }
}

// ---------- kernel P3: CTA-tiled rescore (3-stage ring, smem x-tile + e-chunk) ----------
__global__ __launch_bounds__(256, 1) void rescore_kernel(const float* __restrict__ x,
                                                         float* __restrict__ out, int half)
{
    extern __shared__ __align__(128) char smem[];
    const uint32_t sb = (uint32_t)__cvta_generic_to_shared(smem);
    const int tid = threadIdx.x;
    const int tok = tid & 127;
    const int h   = tid >> 7;              // candidate-parity half
    const int m0  = blockIdx.x * RTOK;
    const int t   = m0 + tok;

    u64 mask = g_mask[t];
    int cand[NCAND], nc = 0;
    while (mask && nc < NCAND) {
        int e = __ffsll((long long)mask) - 1;
        cand[nc++] = e;
        mask &= mask - 1;
    }
    const float2 st = g_tokstats[t];

    #define RISSUE(c) do {                                                     \
        uint32_t base_ = sb + ((c) % RSTAGES) * RSTAGE;                        \
        _Pragma("unroll")                                                      \
        for (int i_ = 0; i_ < 8; i_++) {     /* x: 128 rows x 16 seg */        \
            int idx_ = tid + i_ * 256;                                         \
            int r_ = idx_ >> 4, sg_ = idx_ & 15;                               \
            cp_async16(base_ + r_ * RPITCHB + sg_ * 16,                        \
                       x + (size_t)(m0 + r_) * D + (c) * RKC + sg_ * 4);       \
        }                                                                      \
        _Pragma("unroll")                                                      \
        for (int i_ = 0; i_ < 4; i_++) {     /* e: 64 rows x 16 seg */         \
            int idx_ = tid + i_ * 256;                                         \
            int r_ = idx_ >> 4, sg_ = idx_ & 15;                               \
            cp_async16(base_ + RX_BYTES + r_ * RPITCHB + sg_ * 16,             \
                       g_enorm + (size_t)r_ * D + (c) * RKC + sg_ * 4);        \
        }                                                                      \
    } while (0)

    RISSUE(0); asm volatile("cp.async.commit_group;" ::: "memory");
    RISSUE(1); asm volatile("cp.async.commit_group;" ::: "memory");

    float dacc[NCAND];
    #pragma unroll
    for (int i = 0; i < NCAND; i++) dacc[i] = 0.f;

    for (int c = 0; c < RNCH; c++) {
        asm volatile("cp.async.wait_group 1;" ::: "memory");
        __syncthreads();
        if (c + 2 < RNCH) RISSUE(c + 2);   // stage (c+2)%3: distinct from c%3 and (c+1)%3
        asm volatile("cp.async.commit_group;" ::: "memory");

        const uint32_t base = sb + (c % RSTAGES) * RSTAGE;
        const uint32_t xrow = base + tok * RPITCHB;
        for (int ci = h; ci < nc; ci += 2) {       // this half owns parity-h candidates
            const uint32_t erow = base + RX_BYTES + cand[ci] * RPITCHB;
            float d = dacc[ci];
            #pragma unroll
            for (int j = 0; j < 16; j++) {
                float x0, x1, x2, x3, e0, e1, e2, e3;
                asm("ld.shared.v4.f32 {%0,%1,%2,%3}, [%4];"
                    : "=f"(x0), "=f"(x1), "=f"(x2), "=f"(x3) : "r"(xrow + j * 16));
                asm("ld.shared.v4.f32 {%0,%1,%2,%3}, [%4];"
                    : "=f"(e0), "=f"(e1), "=f"(e2), "=f"(e3) : "r"(erow + j * 16));
                d += x0 * e0 + x1 * e1 + x2 * e2 + x3 * e3;
            }
            dacc[ci] = d;
        }
    }
    asm volatile("cp.async.wait_all;" ::: "memory");

    // per-half top-2 over owned candidates (exact fp32 sims)
    float v1 = -1e30f, v2 = -1e30f;
    int   i1 = -1, i2 = -1;
    for (int ci = h; ci < nc; ci += 2) {
        const float s = st.y * (dacc[ci] - st.x * g_esum[cand[ci]]);
        if (s > v1)      { v2 = v1; i2 = i1; v1 = s; i1 = cand[ci]; }
        else if (s > v2) { v2 = s; i2 = cand[ci]; }
    }
    __syncthreads();
    float4* ex = reinterpret_cast<float4*>(smem);  // [256] merge slots
    ex[tid] = make_float4(v1, __int_as_float(i1), v2, __int_as_float(i2));
    __syncthreads();

    if (tid < 128) {
        float4 p = ex[tid + 128];
        float pv[2] = {p.x, p.z};
        int   pi[2] = {__float_as_int(p.y), __float_as_int(p.w)};
        #pragma unroll
        for (int k = 0; k < 2; k++) {
            if (pv[k] > v1)      { v2 = v1; i2 = i1; v1 = pv[k]; i1 = pi[k]; }
            else if (pv[k] > v2) { v2 = pv[k]; i2 = pi[k]; }
        }
        float e2 = __expf((v2 - v1) * INVT);
        out[2 * t + 0]        = (float)i1;
        out[2 * t + 1]        = (float)i2;
        out[half + 2 * t + 0] = 1.f / (1.f + e2);
        out[half + 2 * t + 1] = e2 / (1.f + e2);
    }
}

// ---------- host ----------
extern "C" void kernel_launch(void* const* d_in, const int* in_sizes, int n_in,
                              void* d_out, int out_size) {
    const float* x   = (const float*)d_in[0];   // [4,4096,2048] fp32
    const float* emb = (const float*)d_in[1];   // [64,2048]     fp32
    float* out = (float*)d_out;
    const int half = out_size / 2;

    cudaFuncSetAttribute(screen_kernel,  cudaFuncAttributeMaxDynamicSharedMemorySize, QSMEM);
    cudaFuncSetAttribute(rescore_kernel, cudaFuncAttributeMaxDynamicSharedMemorySize, RSMEM);

    normalize_experts<<<NEXP, 256>>>(emb);
    quant_kernel<<<NTOK / 8, 256>>>(x);
    screen_kernel<<<NTOK / TMQ, 256, QSMEM>>>();
    rescore_kernel<<<NTOK / RTOK, 256, RSMEM>>>(x, out, half);
}

// round 14
// speedup vs baseline: 1.3045x; 1.3045x over previous
#include <cuda_runtime.h>
#include <math.h>
#include <stdint.h>

#define D        2048
#define NEXP     64
#define NTOK     16384
#define SCALE    21.166666f          // 127/6: LN outputs ~N(0,1), 6-sigma clip = never
#define MARGIN_I 6700                // 15 normalized units * SCALE^2 (~12 sigma_diff)
#define INVT     (1.f / 45.254833995939045f)  // 1/sqrt(2048)

// ---------- int8 screen GEMM geometry ----------
#define TMQ      128                 // tokens per CTA
#define KCQ      128                 // int8 k per chunk
#define QCH      (D / KCQ)           // 16
#define QPITCH   144                 // bytes per smem row (pad)
#define QA_BYTES (TMQ * QPITCH)      // 18432
#define QB_BYTES (NEXP * QPITCH)     // 9216
#define QSTAGE   (QA_BYTES + QB_BYTES)
#define QSTAGES  3
#define QSMEM    (QSTAGES * QSTAGE)  // 82944
#define NCAND    16

__device__ float    g_enorm[NEXP * D];     // normalized experts fp32 (L2-resident, 512KB)
__device__ float    g_esum[NEXP];
__device__ uint32_t g_eq[NEXP * D / 4];    // int8 experts, packed
__device__ uint32_t g_q[(size_t)NTOK * D / 4];  // int8 tokens, packed (32MB)
__device__ float2   g_tokstats[NTOK];      // (mu, rstd)
__device__ unsigned long long g_mask[NTOK];

typedef unsigned long long u64;

__device__ __forceinline__ void cp_async16(uint32_t dst, const void* src) {
    asm volatile("cp.async.cg.shared.global [%0], [%1], 16;"
                 :: "r"(dst), "l"(src) : "memory");
}
__device__ __forceinline__ int dp4a(uint32_t a, uint32_t b, int c) {
    int r;
    asm("dp4a.s32.s32 %0, %1, %2, %3;" : "=r"(r) : "r"(a), "r"(b), "r"(c));
    return r;
}
__device__ __forceinline__ uint32_t q8(float x) {
    int v = __float2int_rn(x * SCALE);
    v = max(-127, min(127, v));
    return (uint32_t)v & 0xFFu;
}
__device__ __forceinline__ float2 block_reduce256_2(float a, float b, float2* red) {
    int tid = threadIdx.x;
    __syncthreads();
    #pragma unroll
    for (int o = 16; o > 0; o >>= 1) {
        a += __shfl_xor_sync(0xffffffffu, a, o);
        b += __shfl_xor_sync(0xffffffffu, b, o);
    }
    if ((tid & 31) == 0) red[tid >> 5] = make_float2(a, b);
    __syncthreads();
    float2 r = (tid < 8) ? red[tid] : make_float2(0.f, 0.f);
    #pragma unroll
    for (int o = 4; o > 0; o >>= 1) {
        r.x += __shfl_xor_sync(0xffffffffu, r.x, o);
        r.y += __shfl_xor_sync(0xffffffffu, r.y, o);
    }
    if (tid == 0) red[0] = r;
    __syncthreads();
    return red[0];
}

// ---------- kernel 0: normalize experts -> fp32 + int8 + sums ----------
__global__ __launch_bounds__(256) void normalize_experts(const float* __restrict__ emb) {
    __shared__ float2 red[8];
    const int e = blockIdx.x, tid = threadIdx.x;
    const float4* row = reinterpret_cast<const float4*>(emb + e * D);
    float4 v0 = row[tid];
    float4 v1 = row[tid + 256];
    float s  = v0.x + v0.y + v0.z + v0.w + v1.x + v1.y + v1.z + v1.w;
    float sq = v0.x*v0.x + v0.y*v0.y + v0.z*v0.z + v0.w*v0.w
             + v1.x*v1.x + v1.y*v1.y + v1.z*v1.z + v1.w*v1.w;
    float2 ssq = block_reduce256_2(s, sq, red);
    const float mu   = ssq.x * (1.f / D);
    const float var  = ssq.y * (1.f / D) - mu * mu;
    const float rstd = rsqrtf(var + 1e-5f);

    float4 n0 = make_float4((v0.x-mu)*rstd, (v0.y-mu)*rstd, (v0.z-mu)*rstd, (v0.w-mu)*rstd);
    float4 n1 = make_float4((v1.x-mu)*rstd, (v1.y-mu)*rstd, (v1.z-mu)*rstd, (v1.w-mu)*rstd);
    float4* o = reinterpret_cast<float4*>(g_enorm + e * D);
    o[tid]       = n0;
    o[tid + 256] = n1;
    g_eq[e * 512 + tid]       = q8(n0.x) | (q8(n0.y) << 8) | (q8(n0.z) << 16) | (q8(n0.w) << 24);
    g_eq[e * 512 + 256 + tid] = q8(n1.x) | (q8(n1.y) << 8) | (q8(n1.z) << 16) | (q8(n1.w) << 24);

    float ls = n0.x+n0.y+n0.z+n0.w + n1.x+n1.y+n1.z+n1.w;
    float2 lz = block_reduce256_2(ls, 0.f, red);
    if (tid == 0) g_esum[e] = lz.x;
}

// ---------- kernel P1: token LN stats + int8 quantize ----------
__global__ __launch_bounds__(256) void quant_kernel(const float* __restrict__ x) {
    const int w    = threadIdx.x >> 5;
    const int lane = threadIdx.x & 31;
    const int t    = blockIdx.x * 8 + w;

    const float4* row = reinterpret_cast<const float4*>(x + (size_t)t * D);
    float4 v[16];
    float s = 0.f, sq = 0.f;
    #pragma unroll
    for (int i = 0; i < 16; i++) {
        v[i] = row[i * 32 + lane];
        s  += v[i].x + v[i].y + v[i].z + v[i].w;
        sq += v[i].x*v[i].x + v[i].y*v[i].y + v[i].z*v[i].z + v[i].w*v[i].w;
    }
    #pragma unroll
    for (int o = 16; o > 0; o >>= 1) {
        s  += __shfl_xor_sync(0xffffffffu, s, o);
        sq += __shfl_xor_sync(0xffffffffu, sq, o);
    }
    const float mu   = s * (1.f / D);
    const float rstd = rsqrtf(sq * (1.f / D) - mu * mu + 1e-5f);

    uint32_t* qrow = g_q + (size_t)t * 512;
    #pragma unroll
    for (int i = 0; i < 16; i++) {
        float a0 = (v[i].x - mu) * rstd, a1 = (v[i].y - mu) * rstd;
        float a2 = (v[i].z - mu) * rstd, a3 = (v[i].w - mu) * rstd;
        qrow[i * 32 + lane] = q8(a0) | (q8(a1) << 8) | (q8(a2) << 16) | (q8(a3) << 24);
    }
    if (lane == 0) g_tokstats[t] = make_float2(mu, rstd);
}

// ---------- kernel P2: int8 dp4a screen GEMM -> candidate masks (UNCHANGED) ----------
__global__ __launch_bounds__(256, 1) void screen_kernel() {
    extern __shared__ __align__(128) char smem[];
    const uint32_t sb = (uint32_t)__cvta_generic_to_shared(smem);
    const int tid = threadIdx.x;
    const int tg  = tid & 15;
    const int eg  = tid >> 4;
    const int m0  = blockIdx.x * TMQ;

    const char* qa = (const char*)g_q + (size_t)m0 * D;
    const char* qb = (const char*)g_eq;

    #define QISSUE(c) do {                                                     \
        uint32_t base_ = sb + ((c) % QSTAGES) * QSTAGE;                        \
        _Pragma("unroll")                                                      \
        for (int i_ = 0; i_ < 4; i_++) {                                       \
            int idx_ = tid + i_ * 256;                                         \
            int r_ = idx_ >> 3, sg_ = idx_ & 7;                                \
            cp_async16(base_ + r_ * QPITCH + sg_ * 16,                         \
                       qa + (size_t)r_ * D + (c) * KCQ + sg_ * 16);            \
        }                                                                      \
        _Pragma("unroll")                                                      \
        for (int i_ = 0; i_ < 2; i_++) {                                       \
            int idx_ = tid + i_ * 256;                                         \
            int r_ = idx_ >> 3, sg_ = idx_ & 7;                                \
            cp_async16(base_ + QA_BYTES + r_ * QPITCH + sg_ * 16,              \
                       qb + (size_t)r_ * D + (c) * KCQ + sg_ * 16);            \
        }                                                                      \
    } while (0)

    QISSUE(0); asm volatile("cp.async.commit_group;" ::: "memory");
    QISSUE(1); asm volatile("cp.async.commit_group;" ::: "memory");

    int acc[8][4];
    #pragma unroll
    for (int i = 0; i < 8; i++)
        #pragma unroll
        for (int j = 0; j < 4; j++) acc[i][j] = 0;

    for (int c = 0; c < QCH; c++) {
        asm volatile("cp.async.wait_group 1;" ::: "memory");
        __syncthreads();
        if (c + 2 < QCH) QISSUE(c + 2);
        asm volatile("cp.async.commit_group;" ::: "memory");

        const uint32_t base  = sb + (c % QSTAGES) * QSTAGE;
        const uint32_t abase = base + tg * QPITCH;
        const uint32_t bbase = base + QA_BYTES + (eg * 4) * QPITCH;

        #pragma unroll
        for (int kq = 0; kq < 8; kq++) {
            uint32_t b0x,b0y,b0z,b0w, b1x,b1y,b1z,b1w, b2x,b2y,b2z,b2w, b3x,b3y,b3z,b3w;
            asm volatile("ld.shared.v4.b32 {%0,%1,%2,%3}, [%4];"
                         : "=r"(b0x),"=r"(b0y),"=r"(b0z),"=r"(b0w) : "r"(bbase + kq*16));
            asm volatile("ld.shared.v4.b32 {%0,%1,%2,%3}, [%4];"
                         : "=r"(b1x),"=r"(b1y),"=r"(b1z),"=r"(b1w) : "r"(bbase + QPITCH + kq*16));
            asm volatile("ld.shared.v4.b32 {%0,%1,%2,%3}, [%4];"
                         : "=r"(b2x),"=r"(b2y),"=r"(b2z),"=r"(b2w) : "r"(bbase + 2*QPITCH + kq*16));
            asm volatile("ld.shared.v4.b32 {%0,%1,%2,%3}, [%4];"
                         : "=r"(b3x),"=r"(b3y),"=r"(b3z),"=r"(b3w) : "r"(bbase + 3*QPITCH + kq*16));
            #pragma unroll
            for (int i = 0; i < 8; i++) {
                uint32_t ax, ay, az, aw;
                asm volatile("ld.shared.v4.b32 {%0,%1,%2,%3}, [%4];"
                             : "=r"(ax),"=r"(ay),"=r"(az),"=r"(aw)
                             : "r"(abase + i * 16 * QPITCH + kq * 16));
                acc[i][0] = dp4a(aw, b0w, dp4a(az, b0z, dp4a(ay, b0y, dp4a(ax, b0x, acc[i][0]))));
                acc[i][1] = dp4a(aw, b1w, dp4a(az, b1z, dp4a(ay, b1y, dp4a(ax, b1x, acc[i][1]))));
                acc[i][2] = dp4a(aw, b2w, dp4a(az, b2z, dp4a(ay, b2y, dp4a(ax, b2x, acc[i][2]))));
                acc[i][3] = dp4a(aw, b3w, dp4a(az, b3z, dp4a(ay, b3y, dp4a(ax, b3x, acc[i][3]))));
            }
        }
    }
    asm volatile("cp.async.wait_all;" ::: "memory");
    __syncthreads();

    int* simI = reinterpret_cast<int*>(smem);      // [128][68]
    #pragma unroll
    for (int i = 0; i < 8; i++)
        asm volatile("st.shared.v4.b32 [%0], {%1,%2,%3,%4};"
                     :: "r"(sb + ((i * 16 + tg) * 68 + eg * 4) * 4),
                        "r"(acc[i][0]), "r"(acc[i][1]), "r"(acc[i][2]), "r"(acc[i][3])
                     : "memory");
    __syncthreads();

    if (tid < TMQ) {
        const int* r = simI + tid * 68;
        int v1 = -2147483647, v2 = -2147483647;
        #pragma unroll 8
        for (int e = 0; e < NEXP; e++) {
            int v = r[e];
            if (v > v1)      { v2 = v1; v1 = v; }
            else if (v > v2) { v2 = v; }
        }
        const int thr = v2 - MARGIN_I;
        u64 mask = 0ull; int cnt = 0;
        #pragma unroll 8
        for (int e = 0; e < NEXP; e++)
            if (r[e] >= thr) { mask |= 1ull << e; cnt++; }
        if (cnt > NCAND) {
            u64 keep = 0ull;
            for (int it = 0; it < NCAND; it++) {
                int best = -2147483647, bi = -1;
                for (int e = 0; e < NEXP; e++)
                    if ((mask >> e) & 1ull)
                        if (!((keep >> e) & 1ull) && r[e] > best) { best = r[e]; bi = e; }
                keep |= 1ull << bi;
            }
            mask = keep;
        }
        g_mask[m0 + tid] = mask;
    }
}

// ---------- kernel P3: 2-warps-per-token rescore (half x row in regs, ~60 regs) ----------
__global__ __launch_bounds__(256) void rescore_kernel(const float* __restrict__ x,
                                                      float* __restrict__ out, int half)
{
    __shared__ float ps[4][2][NCAND];      // [token-in-CTA][row-half][candidate]
    const int tid  = threadIdx.x;
    const int w    = tid >> 5;
    const int lane = tid & 31;
    const int tk   = w >> 1;               // token slot 0..3
    const int h    = w & 1;                // row half 0..1
    const int t    = blockIdx.x * 4 + tk;

    u64 mask = g_mask[t];
    int cand[NCAND], nc = 0;
    while (mask && nc < NCAND) {
        int e = __ffsll((long long)mask) - 1;
        cand[nc++] = e;
        mask &= mask - 1;
    }

    // this warp's half of the x row: 1024 floats = 8 float4 per lane (coalesced)
    const float4* row = reinterpret_cast<const float4*>(x + (size_t)t * D) + h * 256;
    float4 v[8];
    #pragma unroll
    for (int i = 0; i < 8; i++) v[i] = row[i * 32 + lane];

    for (int ci = 0; ci < nc; ci++) {
        const float4* er = reinterpret_cast<const float4*>(g_enorm + cand[ci] * D) + h * 256;
        float d = 0.f;
        #pragma unroll
        for (int i = 0; i < 8; i++) {
            float4 ev = er[i * 32 + lane];              // L2-resident expert half-row
            d += v[i].x * ev.x + v[i].y * ev.y + v[i].z * ev.z + v[i].w * ev.w;
        }
        #pragma unroll
        for (int o = 16; o > 0; o >>= 1) d += __shfl_xor_sync(0xffffffffu, d, o);
        if (lane == 0) ps[tk][h][ci] = d;
    }
    __syncthreads();

    if (h == 0 && lane == 0) {                          // even warp finalizes its token
        const float2 st = g_tokstats[t];
        float v1 = -1e30f, v2 = -1e30f;
        int   i1 = 0, i2 = 0;
        for (int ci = 0; ci < nc; ci++) {
            const float d = ps[tk][0][ci] + ps[tk][1][ci];
            const float s = st.y * (d - st.x * g_esum[cand[ci]]);
            if (s > v1)      { v2 = v1; i2 = i1; v1 = s; i1 = cand[ci]; }
            else if (s > v2) { v2 = s; i2 = cand[ci]; }
        }
        float e2 = __expf((v2 - v1) * INVT);
        out[2 * t + 0]        = (float)i1;
        out[2 * t + 1]        = (float)i2;
        out[half + 2 * t + 0] = 1.f / (1.f + e2);
        out[half + 2 * t + 1] = e2 / (1.f + e2);
    }
}

// ---------- host ----------
extern "C" void kernel_launch(void* const* d_in, const int* in_sizes, int n_in,
                              void* d_out, int out_size) {
    const float* x   = (const float*)d_in[0];   // [4,4096,2048] fp32
    const float* emb = (const float*)d_in[1];   // [64,2048]     fp32
    float* out = (float*)d_out;
    const int half = out_size / 2;

    cudaFuncSetAttribute(screen_kernel, cudaFuncAttributeMaxDynamicSharedMemorySize, QSMEM);

    normalize_experts<<<NEXP, 256>>>(emb);
    quant_kernel<<<NTOK / 8, 256>>>(x);
    screen_kernel<<<NTOK / TMQ, 256, QSMEM>>>();
    rescore_kernel<<<NTOK / 4, 256>>>(x, out, half);
}